// round 15
// baseline (speedup 1.0000x reference)
#include <cuda_runtime.h>
#include <math.h>

#define NA     4096
#define CUTF   5.0f
#define CUT2   25.0f
#define MAGIC  12582912.0f   // 1.5*2^23 : (x+MAGIC)-MAGIC == rint-to-even(x), |x| < 2^22
#define NCM    1024          // scan domain (real ncells <= 1000)
#define NB     256           // blocks, 16 rows each; 2 blocks/SM -> 100% occ
#define NT     1024          // 32 warps/block; 2 warps per row in phase B

// Dynamic smem layout (bytes)
#define OFF_SCL   0                         // float4[NA]   65536  cell-sorted atoms
#define OFF_PERM  (OFF_SCL + NA * 16)       // int[NA]      16384  orig -> sorted (temp: cell id)
#define OFF_CS    (OFF_PERM + NA * 4)       // int[NCM+8]    4128  cell starts
#define OFF_HIST  (OFF_CS + (NCM + 8) * 4)  // int[NCM]      4096  hist / cursors
#define OFF_MASK  (OFF_HIST + NCM * 4)      // uint[16][128]  8192 row masks
#define SMEM_BYTES (OFF_MASK + 16 * 128 * 4)   // ~96.3 KB -> 2 blocks/SM

// Sole global scratch: decoupled-lookback descriptors. Deterministic kernel =>
// stale values from a previous call are identical => correct; no reset needed.
__device__ int g_look[NB];
#define LOOK_A   (1 << 30)
#define LOOK_P   (1 << 31)
#define LOOK_VAL ((1 << 24) - 1)

// Multiply-form binning: f = nc/L precomputed; used consistently everywhere.
__device__ __forceinline__ int cell1m(float x, float f, int nc) {
    int c = (int)(x * f);
    if (c < 0) c = 0;
    if (c >= nc) c = nc - 1;
    return c;
}

// Diagonal-box minimum image, bit-matching reference op order (validated R2-R13).
__device__ __forceinline__ float pair_d2_diag(float dx, float dy, float dz,
                                              float i0, float i1, float i2,
                                              float L0, float L1, float L2,
                                              float& ox, float& oy, float& oz) {
    float rx = __fsub_rn(__fadd_rn(__fmul_rn(dx, i0), MAGIC), MAGIC);
    float ry = __fsub_rn(__fadd_rn(__fmul_rn(dy, i1), MAGIC), MAGIC);
    float rz = __fsub_rn(__fadd_rn(__fmul_rn(dz, i2), MAGIC), MAGIC);
    ox = __fsub_rn(dx, __fmul_rn(rx, L0));
    oy = __fsub_rn(dy, __fmul_rn(ry, L1));
    oz = __fsub_rn(dz, __fmul_rn(rz, L2));
    return __fadd_rn(__fadd_rn(__fmul_rn(ox, ox), __fmul_rn(oy, oy)), __fmul_rn(oz, oz));
}

__global__ void __launch_bounds__(NT, 2)
k_all(const float* __restrict__ pos, const float* __restrict__ box,
      float* __restrict__ out, int P) {
    extern __shared__ __align__(16) char smem[];
    float4*  scl  = (float4*)(smem + OFF_SCL);
    int*     perm = (int*)(smem + OFF_PERM);
    int*     cs   = (int*)(smem + OFF_CS);
    int*     hist = (int*)(smem + OFF_HIST);
    unsigned (*smask)[128] = (unsigned (*)[128])(smem + OFF_MASK);

    __shared__ float sinv[3];
    __shared__ int   scnt[16], soff[16], swsum[32];

    const int tid = threadIdx.x, bid = blockIdx.x;
    const int w = tid >> 5, lane = tid & 31;

    // ---- pad entire output (independent; fenced before our publish) ----
    {
        float4* out4 = (float4*)out;
        const int pairs4 = (2 * P) >> 2, total4 = (6 * P) >> 2;
        const float4 neg1 = make_float4(-1.f, -1.f, -1.f, -1.f);
        const float4 zero = make_float4(0.f, 0.f, 0.f, 0.f);
        for (int k = bid * NT + tid; k < total4; k += NB * NT)
            out4[k] = (k < pairs4) ? neg1 : zero;
    }

    // ---- box constants (same validated op order as R2-R13) ----
    if (tid == 0) {
        float b[9];
#pragma unroll
        for (int i = 0; i < 9; i++) b[i] = box[i];
        float c00 =  (b[4]*b[8] - b[5]*b[7]);
        float c01 = -(b[3]*b[8] - b[5]*b[6]);
        float c02 =  (b[3]*b[7] - b[4]*b[6]);
        float det = b[0]*c00 + b[1]*c01 + b[2]*c02;
        sinv[0] = __fdiv_rn(c00, det);
        sinv[1] = __fdiv_rn((b[0]*b[8] - b[2]*b[6]), det);
        sinv[2] = __fdiv_rn((b[0]*b[4] - b[1]*b[3]), det);
    }
    const float L0 = box[0], L1 = box[4], L2 = box[8];
    int ncx = (int)(L0 / CUTF); ncx = max(3, min(ncx, 10));
    int ncy = (int)(L1 / CUTF); ncy = max(3, min(ncy, 10));
    int ncz = (int)(L2 / CUTF); ncz = max(3, min(ncz, 10));
    const float fx = __fdiv_rn((float)ncx, L0);
    const float fy = __fdiv_rn((float)ncy, L1);
    const float fz = __fdiv_rn((float)ncz, L2);

    hist[tid] = 0;
    __syncthreads();

    // ===== Phase A: block-local counting sort (reg-light, 2 passes) =======
#pragma unroll
    for (int q = 0; q < 4; q++) {
        const int a = tid + q * NT;
        const int c = (cell1m(pos[3*a+2], fz, ncz) * ncy
                     + cell1m(pos[3*a+1], fy, ncy)) * ncx
                     + cell1m(pos[3*a+0], fx, ncx);
        perm[a] = c;                    // stage cell id (rewritten below)
        atomicAdd(&hist[c], 1);
    }
    __syncthreads();

    // block scan of 1024 hist entries -> cs
    {
        const int v = hist[tid];
        int incl = v;
#pragma unroll
        for (int d = 1; d < 32; d <<= 1) {
            int u = __shfl_up_sync(0xffffffffu, incl, d);
            if (lane >= d) incl += u;
        }
        if (lane == 31) swsum[w] = incl;
        __syncthreads();
        if (w == 0) {
            int wv = swsum[lane], wincl = wv;
#pragma unroll
            for (int d = 1; d < 32; d <<= 1) {
                int u = __shfl_up_sync(0xffffffffu, wincl, d);
                if (lane >= d) wincl += u;
            }
            swsum[lane] = wincl - wv;
        }
        __syncthreads();
        cs[tid] = swsum[w] + incl - v;
        __syncthreads();
    }
    hist[tid] = 0;                      // reuse as per-cell fill cursors
    __syncthreads();
#pragma unroll
    for (int q = 0; q < 4; q++) {
        const int a = tid + q * NT;
        const int c = perm[a];
        const int dst = cs[c] + atomicAdd(&hist[c], 1);
        scl[dst] = make_float4(pos[3*a+0], pos[3*a+1], pos[3*a+2],
                               __int_as_float(a));   // pos reload: L2-hot
        perm[a] = dst;
    }
    // zero the 16 row masks (2048 words / 1024 threads)
    {
        unsigned* mw = (unsigned*)smask;
        mw[tid] = 0u; mw[tid + NT] = 0u;
    }
    __syncthreads();

    // ===== Phase B: 2 warps per row, split by (dz,dy)-plane parity ========
    const float i0 = sinv[0], i1 = sinv[1], i2 = sinv[2];
    {
        const int lr   = w >> 1;              // local row [0,16)
        const int half = w & 1;
        const int row  = bid * 16 + lr;
        const float4 rp = scl[perm[row]];
        const float xi = rp.x, yi = rp.y, zi = rp.z;
        const int cx = cell1m(xi, fx, ncx);
        const int cy = cell1m(yi, fy, ncy);
        const int cz = cell1m(zi, fz, ncz);

        auto seg = [&](int s, int e) {
            for (int k = s + lane; k < e; k += 32) {
                const float4 p = scl[k];            // LDS.128
                const int jo = __float_as_int(p.w);
                float ox, oy, oz;
                const float d2 = pair_d2_diag(xi - p.x, yi - p.y, zi - p.z,
                                              i0, i1, i2, L0, L1, L2, ox, oy, oz);
                if (jo > row && d2 < CUT2)
                    atomicOr(&smask[lr][jo >> 5], 1u << (jo & 31));
            }
        };

        int it = 0;
        for (int dz = -1; dz <= 1; dz++) {
            int czz = cz + dz; czz += (czz < 0) ? ncz : 0; czz -= (czz >= ncz) ? ncz : 0;
            for (int dy = -1; dy <= 1; dy++, it++) {
                if ((it & 1) != half) continue;    // plane-parity split
                int cyy = cy + dy; cyy += (cyy < 0) ? ncy : 0; cyy -= (cyy >= ncy) ? ncy : 0;
                const int rb = (czz * ncy + cyy) * ncx;
                if (cx > 0 && cx < ncx - 1) {
                    seg(cs[rb + cx - 1], cs[rb + cx + 2]);
                } else if (cx == 0) {
                    seg(cs[rb],           cs[rb + 2]);
                    seg(cs[rb + ncx - 1], cs[rb + ncx]);
                } else {
                    seg(cs[rb + ncx - 2], cs[rb + ncx]);
                    seg(cs[rb],           cs[rb + 1]);
                }
            }
        }
    }
    __threadfence();          // order pad stores before our publish
    __syncthreads();          // masks complete (both warps of each row)

    // counts: warps 0-15, one row each
    if (w < 16) {
        const uint4 mv = ((const uint4*)smask[w])[lane];
        int c = __popc(mv.x) + __popc(mv.y) + __popc(mv.z) + __popc(mv.w);
        c = __reduce_add_sync(0xffffffffu, c);
        if (lane == 0) scnt[w] = c;
    }
    __syncthreads();

    // ===== Phase C: 16-row block scan + decoupled lookback (warp 0) =======
    if (w == 0) {
        const int cv = (lane < 16) ? scnt[lane] : 0;
        int incl = cv;
#pragma unroll
        for (int d = 1; d < 32; d <<= 1) {
            int u = __shfl_up_sync(0xffffffffu, incl, d);
            if (lane >= d) incl += u;
        }
        const int agg = __shfl_sync(0xffffffffu, incl, 15);
        if (lane == 0)
            atomicExch(&g_look[bid], LOOK_A | agg);

        int excl = 0;                               // warp-parallel lookback
        if (bid > 0) {
            int k = bid - 1;
            while (true) {
                const int idx = k - lane;
                int v;
                if (idx >= 0) {
                    do { v = *(volatile int*)&g_look[idx]; }
                    while (!(v & (LOOK_A | LOOK_P)));
                } else v = LOOK_P;
                const bool isP = (v & LOOK_P) != 0;
                const unsigned pm = __ballot_sync(0xffffffffu, isP);
                int contrib;
                if (pm) {
                    const int pl = __ffs(pm) - 1;
                    contrib = (lane < pl) ? (v & LOOK_VAL)
                            : (lane == pl ? ((idx >= 0) ? (v & LOOK_VAL) : 0) : 0);
                } else {
                    contrib = v & LOOK_VAL;
                }
                excl += __reduce_add_sync(0xffffffffu, contrib);
                if (pm) break;
                k -= 32;
            }
        }
        if (lane < 16) soff[lane] = excl + incl - cv;
        if (lane == 0) {
            atomicExch(&g_look[bid], LOOK_P | (excl + agg));
            if (bid == NB - 1) out[6 * P] = (float)(excl + agg);   // n_pairs
        }
    }
    __syncthreads();

    // ===== Phase D: ordered fill, warps 0-15 (one row each) ===============
    if (w < 16) {
        const int row = bid * 16 + w;
        const float4 rp = scl[perm[row]];
        const float xi = rp.x, yi = rp.y, zi = rp.z;
        const uint4 mv = ((const uint4*)smask[w])[lane];
        const int c = __popc(mv.x) + __popc(mv.y) + __popc(mv.z) + __popc(mv.w);
        int incl = c;
#pragma unroll
        for (int d = 1; d < 32; d <<= 1) {
            int u = __shfl_up_sync(0xffffffffu, incl, d);
            if (lane >= d) incl += u;
        }
        int idx = soff[w] + incl - c;

        unsigned wsv[4] = {mv.x, mv.y, mv.z, mv.w};
#pragma unroll
        for (int q = 0; q < 4; q++) {
            unsigned wv = wsv[q];
            while (wv) {
                const int b = __ffs(wv) - 1; wv &= (wv - 1);
                const int j = 128 * lane + 32 * q + b;
                const float4 pj = scl[perm[j]];
                float ox, oy, oz;
                const float d2 = pair_d2_diag(xi - pj.x, yi - pj.y, zi - pj.z,
                                              i0, i1, i2, L0, L1, L2, ox, oy, oz);
                out[idx]             = (float)row;
                out[(size_t)P + idx] = (float)j;
                float* dp = out + (size_t)2 * P + 3 * (size_t)idx;
                dp[0] = ox; dp[1] = oy; dp[2] = oz;
                out[(size_t)5 * P + idx] = sqrtf(d2);
                idx++;
            }
        }
    }
}

extern "C" void kernel_launch(void* const* d_in, const int* in_sizes, int n_in,
                              void* d_out, int out_size) {
    const float* pos = (const float*)d_in[0];   // [4096, 3] float32
    const float* box = (const float*)d_in[1];   // [3, 3]   float32
    float* out = (float*)d_out;
    const int P = (out_size - 1) / 6;           // MAX_NUM_PAIRS

    cudaFuncSetAttribute(k_all, cudaFuncAttributeMaxDynamicSharedMemorySize,
                         SMEM_BYTES);           // host attr set; capture-safe
    k_all<<<NB, NT, SMEM_BYTES>>>(pos, box, out, P);
}

// round 16
// speedup vs baseline: 1.2280x; 1.2280x over previous
#include <cuda_runtime.h>
#include <math.h>

#define NA     4096
#define CUTF   5.0f
#define CUT2   25.0f
#define THRA   25.05f        // prefilter threshold (quantization bound 0.011)
#define MAGIC  12582912.0f   // 1.5*2^23 : (x+MAGIC)-MAGIC == rint-to-even(x)
#define NCM    1024          // scan domain (real ncells <= 1000)
#define NB     128           // blocks, 32 rows each (co-resident on 148 SMs)
#define NT     1024          // 32 warps/block, 1 row/warp

// Dynamic smem layout (bytes)
#define OFF_SCL   0                         // float4[NA]   65536 cell-sorted atoms
#define OFF_SQC   (OFF_SCL + NA * 16)       // uint2[NA]    32768 quantized atoms
#define OFF_PERM  (OFF_SQC + NA * 8)        // int[NA]      16384 orig -> sorted
#define OFF_CS    (OFF_PERM + NA * 4)       // int[NCM+8]    4128 cell starts
#define OFF_HIST  (OFF_CS + (NCM + 8) * 4)  // int[NCM]      4096 hist / cursors
#define OFF_MASK  (OFF_HIST + NCM * 4)      // uint[32][128] 16384 row masks
#define SMEM_BYTES (OFF_MASK + 32 * 128 * 4)   // ~137 KB -> 1 block/SM

// Sole global scratch: decoupled-lookback descriptors. Deterministic kernel =>
// stale values from a previous call are identical => correct; no reset needed.
__device__ int g_look[NB];
#define LOOK_A   (1 << 30)
#define LOOK_P   (1 << 31)
#define LOOK_VAL ((1 << 24) - 1)

// Multiply-form binning (from FLOAT coords; coverage proof relies on this).
__device__ __forceinline__ int cell1m(float x, float f, int nc) {
    int c = (int)(x * f);
    if (c < 0) c = 0;
    if (c >= nc) c = nc - 1;
    return c;
}

// Diagonal-box minimum image, bit-matching reference op order (validated R2-R14).
__device__ __forceinline__ float pair_d2_diag(float dx, float dy, float dz,
                                              float i0, float i1, float i2,
                                              float L0, float L1, float L2,
                                              float& ox, float& oy, float& oz) {
    float rx = __fsub_rn(__fadd_rn(__fmul_rn(dx, i0), MAGIC), MAGIC);
    float ry = __fsub_rn(__fadd_rn(__fmul_rn(dy, i1), MAGIC), MAGIC);
    float rz = __fsub_rn(__fadd_rn(__fmul_rn(dz, i2), MAGIC), MAGIC);
    ox = __fsub_rn(dx, __fmul_rn(rx, L0));
    oy = __fsub_rn(dy, __fmul_rn(ry, L1));
    oz = __fsub_rn(dz, __fmul_rn(rz, L2));
    return __fadd_rn(__fadd_rn(__fmul_rn(ox, ox), __fmul_rn(oy, oy)), __fmul_rn(oz, oz));
}

__global__ void __launch_bounds__(NT)
k_all(const float* __restrict__ pos, const float* __restrict__ box,
      float* __restrict__ out, int P) {
    extern __shared__ __align__(16) char smem[];
    float4*  scl  = (float4*)(smem + OFF_SCL);
    uint2*   sqc  = (uint2*)(smem + OFF_SQC);
    int*     perm = (int*)(smem + OFF_PERM);
    int*     cs   = (int*)(smem + OFF_CS);
    int*     hist = (int*)(smem + OFF_HIST);
    unsigned (*smask)[128] = (unsigned (*)[128])(smem + OFF_MASK);

    __shared__ float sinv[3];
    __shared__ int   scnt[32], soff[32], swsum[32];

    const int tid = threadIdx.x, bid = blockIdx.x;
    const int w = tid >> 5, lane = tid & 31;

    // ---- pad entire output (independent; fenced before our publish) ----
    {
        float4* out4 = (float4*)out;
        const int pairs4 = (2 * P) >> 2, total4 = (6 * P) >> 2;
        const float4 neg1 = make_float4(-1.f, -1.f, -1.f, -1.f);
        const float4 zero = make_float4(0.f, 0.f, 0.f, 0.f);
        for (int k = bid * NT + tid; k < total4; k += NB * NT)
            out4[k] = (k < pairs4) ? neg1 : zero;
    }

    // ---- box constants (same validated op order as R2-R14) ----
    if (tid == 0) {
        float b[9];
#pragma unroll
        for (int i = 0; i < 9; i++) b[i] = box[i];
        float c00 =  (b[4]*b[8] - b[5]*b[7]);
        float c01 = -(b[3]*b[8] - b[5]*b[6]);
        float c02 =  (b[3]*b[7] - b[4]*b[6]);
        float det = b[0]*c00 + b[1]*c01 + b[2]*c02;
        sinv[0] = __fdiv_rn(c00, det);
        sinv[1] = __fdiv_rn((b[0]*b[8] - b[2]*b[6]), det);
        sinv[2] = __fdiv_rn((b[0]*b[4] - b[1]*b[3]), det);
    }
    const float L0 = box[0], L1 = box[4], L2 = box[8];
    int ncx = (int)(L0 / CUTF); ncx = max(3, min(ncx, 10));
    int ncy = (int)(L1 / CUTF); ncy = max(3, min(ncy, 10));
    int ncz = (int)(L2 / CUTF); ncz = max(3, min(ncz, 10));
    const float fx = __fdiv_rn((float)ncx, L0);
    const float fy = __fdiv_rn((float)ncy, L1);
    const float fz = __fdiv_rn((float)ncz, L2);
    const float qsx = __fdiv_rn(65536.0f, L0);     // quantization scales
    const float qsy = __fdiv_rn(65536.0f, L1);
    const float qsz = __fdiv_rn(65536.0f, L2);
    const float ux = L0 * (1.0f / 65536.0f);       // dequant per-axis
    const float uy = L1 * (1.0f / 65536.0f);
    const float uz = L2 * (1.0f / 65536.0f);

    hist[tid] = 0;
    __syncthreads();

    // ===== Phase A: block-local counting sort (reg-light, 2 passes) =======
#pragma unroll
    for (int q = 0; q < 4; q++) {
        const int a = tid + q * NT;
        const int c = (cell1m(pos[3*a+2], fz, ncz) * ncy
                     + cell1m(pos[3*a+1], fy, ncy)) * ncx
                     + cell1m(pos[3*a+0], fx, ncx);
        perm[a] = c;                    // stage cell id (rewritten below)
        atomicAdd(&hist[c], 1);
    }
    __syncthreads();

    // block scan of 1024 hist entries -> cs
    {
        const int v = hist[tid];
        int incl = v;
#pragma unroll
        for (int d = 1; d < 32; d <<= 1) {
            int u = __shfl_up_sync(0xffffffffu, incl, d);
            if (lane >= d) incl += u;
        }
        if (lane == 31) swsum[w] = incl;
        __syncthreads();
        if (w == 0) {
            int wv = swsum[lane], wincl = wv;
#pragma unroll
            for (int d = 1; d < 32; d <<= 1) {
                int u = __shfl_up_sync(0xffffffffu, wincl, d);
                if (lane >= d) wincl += u;
            }
            swsum[lane] = wincl - wv;
        }
        __syncthreads();
        cs[tid] = swsum[w] + incl - v;
        __syncthreads();
    }
    hist[tid] = 0;                      // reuse as per-cell fill cursors
    __syncthreads();
#pragma unroll
    for (int q = 0; q < 4; q++) {
        const int a = tid + q * NT;
        const int c = perm[a];
        const int dst = cs[c] + atomicAdd(&hist[c], 1);
        const float x = pos[3*a+0], y = pos[3*a+1], z = pos[3*a+2];  // L2-hot
        scl[dst] = make_float4(x, y, z, __int_as_float(a));
        const unsigned qx = (unsigned)__float2int_rn(x * qsx) & 0xFFFFu;
        const unsigned qy = (unsigned)__float2int_rn(y * qsy) & 0xFFFFu;
        const unsigned qz = (unsigned)__float2int_rn(z * qsz) & 0xFFFFu;
        sqc[dst] = make_uint2((qy << 16) | qx, qz);
        perm[a] = dst;
    }
    // zero the 32 row masks (4096 words / 1024 threads)
    {
        unsigned* mw = (unsigned*)smask;
#pragma unroll
        for (int q = 0; q < 4; q++) mw[tid + q * NT] = 0u;
    }
    __syncthreads();

    // ======= Phase B: count this warp's row (quantized prefilter) =========
    const float i0 = sinv[0], i1 = sinv[1], i2 = sinv[2];
    const int row = bid * 32 + w;
    float xi, yi, zi;
    {
        const int prow = perm[row];
        const float4 rp = scl[prow];
        const uint2  rq = sqc[prow];
        xi = rp.x; yi = rp.y; zi = rp.z;
        const unsigned qxyi = rq.x, qzi = rq.y;
        const int cx = cell1m(xi, fx, ncx);
        const int cy = cell1m(yi, fy, ncy);
        const int cz = cell1m(zi, fz, ncz);

        auto seg = [&](int s, int e) {
            for (int k = s + lane; k < e; k += 32) {
                const uint2 qv = sqc[k];               // LDS.64: 2 crossbar cyc
                const unsigned dxy = __vsub2(qxyi, qv.x);  // exact 16-bit wrap
                const int dqx = (int)(dxy << 16) >> 16;
                const int dqy = (int)dxy >> 16;
                const int dqz = (int)((qzi - qv.y) << 16) >> 16;
                const float fdx = (float)dqx * ux;
                const float fdy = (float)dqy * uy;
                const float fdz = (float)dqz * uz;
                const float d2a = fmaf(fdx, fdx, fmaf(fdy, fdy, fdz * fdz));
                if (d2a < THRA) {                      // ~15% survivors
                    const float4 p = scl[k];           // exact, bit-matching
                    const int jo = __float_as_int(p.w);
                    float ox, oy, oz;
                    const float d2 = pair_d2_diag(xi - p.x, yi - p.y, zi - p.z,
                                                  i0, i1, i2, L0, L1, L2,
                                                  ox, oy, oz);
                    if (jo > row && d2 < CUT2)
                        atomicOr(&smask[w][jo >> 5], 1u << (jo & 31));
                }
            }
        };

        for (int dz = -1; dz <= 1; dz++) {
            int czz = cz + dz; czz += (czz < 0) ? ncz : 0; czz -= (czz >= ncz) ? ncz : 0;
            for (int dy = -1; dy <= 1; dy++) {
                int cyy = cy + dy; cyy += (cyy < 0) ? ncy : 0; cyy -= (cyy >= ncy) ? ncy : 0;
                const int rb = (czz * ncy + cyy) * ncx;
                if (cx > 0 && cx < ncx - 1) {           // 3 x-cells contiguous
                    seg(cs[rb + cx - 1], cs[rb + cx + 2]);
                } else if (cx == 0) {                   // wrap low
                    seg(cs[rb],           cs[rb + 2]);
                    seg(cs[rb + ncx - 1], cs[rb + ncx]);
                } else {                                // wrap high
                    seg(cs[rb + ncx - 2], cs[rb + ncx]);
                    seg(cs[rb],           cs[rb + 1]);
                }
            }
        }
        __syncwarp();

        int c = 0;
#pragma unroll
        for (int q = 0; q < 4; q++) c += __popc(smask[w][q * 32 + lane]);
        c = __reduce_add_sync(0xffffffffu, c);
        if (lane == 0) scnt[w] = c;
    }
    __threadfence();          // order this thread's pad stores before publish
    __syncthreads();

    // ============ Phase C: block scan + decoupled lookback ================
    if (w == 0) {
        const int cv = scnt[lane];
        int incl = cv;
#pragma unroll
        for (int d = 1; d < 32; d <<= 1) {
            int u = __shfl_up_sync(0xffffffffu, incl, d);
            if (lane >= d) incl += u;
        }
        const int agg = __shfl_sync(0xffffffffu, incl, 31);
        if (lane == 0)
            atomicExch(&g_look[bid], LOOK_A | agg);

        int excl = 0;                                  // warp-parallel lookback
        if (bid > 0) {
            int k = bid - 1;
            while (true) {
                const int idx = k - lane;
                int v;
                if (idx >= 0) {
                    do { v = *(volatile int*)&g_look[idx]; }
                    while (!(v & (LOOK_A | LOOK_P)));
                } else v = LOOK_P;
                const bool isP = (v & LOOK_P) != 0;
                const unsigned pm = __ballot_sync(0xffffffffu, isP);
                int contrib;
                if (pm) {
                    const int pl = __ffs(pm) - 1;
                    contrib = (lane < pl) ? (v & LOOK_VAL)
                            : (lane == pl ? ((idx >= 0) ? (v & LOOK_VAL) : 0) : 0);
                } else {
                    contrib = v & LOOK_VAL;
                }
                excl += __reduce_add_sync(0xffffffffu, contrib);
                if (pm) break;
                k -= 32;
            }
        }
        soff[lane] = excl + incl - cv;
        if (lane == 0) {
            atomicExch(&g_look[bid], LOOK_P | (excl + agg));
            if (bid == NB - 1) out[6 * P] = (float)(excl + agg);   // n_pairs
        }
    }
    __syncthreads();

    // ================= Phase D: ordered fill from smem mask ===============
    {
        const uint4 mv = ((const uint4*)smask[w])[lane];
        const int c = __popc(mv.x) + __popc(mv.y) + __popc(mv.z) + __popc(mv.w);
        int incl = c;
#pragma unroll
        for (int d = 1; d < 32; d <<= 1) {
            int u = __shfl_up_sync(0xffffffffu, incl, d);
            if (lane >= d) incl += u;
        }
        int idx = soff[w] + incl - c;

        unsigned wsv[4] = {mv.x, mv.y, mv.z, mv.w};
#pragma unroll
        for (int q = 0; q < 4; q++) {
            unsigned wv = wsv[q];
            while (wv) {
                const int b = __ffs(wv) - 1; wv &= (wv - 1);
                const int j = 128 * lane + 32 * q + b;
                const float4 pj = scl[perm[j]];
                float ox, oy, oz;
                const float d2 = pair_d2_diag(xi - pj.x, yi - pj.y, zi - pj.z,
                                              i0, i1, i2, L0, L1, L2, ox, oy, oz);
                out[idx]             = (float)row;
                out[(size_t)P + idx] = (float)j;
                float* dp = out + (size_t)2 * P + 3 * (size_t)idx;
                dp[0] = ox; dp[1] = oy; dp[2] = oz;
                out[(size_t)5 * P + idx] = sqrtf(d2);
                idx++;
            }
        }
    }
}

extern "C" void kernel_launch(void* const* d_in, const int* in_sizes, int n_in,
                              void* d_out, int out_size) {
    const float* pos = (const float*)d_in[0];   // [4096, 3] float32
    const float* box = (const float*)d_in[1];   // [3, 3]   float32
    float* out = (float*)d_out;
    const int P = (out_size - 1) / 6;           // MAX_NUM_PAIRS

    cudaFuncSetAttribute(k_all, cudaFuncAttributeMaxDynamicSharedMemorySize,
                         SMEM_BYTES);           // host attr set; capture-safe
    k_all<<<NB, NT, SMEM_BYTES>>>(pos, box, out, P);
}